// round 4
// baseline (speedup 1.0000x reference)
#include <cuda_runtime.h>

// ---------------------------------------------------------------------------
// B=16, N=7, Lq=256, Lp=512, D=768, S=12, Wq=200, Wp=400
// word slots: q 3200, p 6400, n 44800 -> 54400
// out floats: q_pooled[0,12288) p_pooled[12288,24576)
//             q_logits[24576,62976) p_logits[62976,139776) n_pooled[139776,225792)
//
// SINGLE persistent fused kernel:
//   phase1 chunk (64 tokens): per-token projection h@W -> g_acc atomics
//   last phase1 chunk of a sample -> inline per-sample softmax -> g_coef, flag
//   phase3 chunk (64 tokens): pooled += coef[wid]*h  (reads h from L2: the
//     ticket order places phase3(c) ~128 chunks (~25MB) after phase1(c))
// ---------------------------------------------------------------------------
#define TOTAL_WORDS 54400
#define OFF_QPOOL 0
#define OFF_PPOOL 12288
#define OFF_QLOG  24576
#define OFF_PLOG  62976
#define OFF_NPOOL 139776

__device__ float g_acc[TOTAL_WORDS * 13];   // 12 logit sums + count
__device__ float g_coef[TOTAL_WORDS];
__device__ unsigned g_ctrl[512];            // [0]=ticket  [16+s]=cnt  [256+s]=flag

typedef unsigned long long u64;

__device__ __forceinline__ u64 pack2(float x) {
    u64 r; asm("mov.b64 %0, {%1, %1};" : "=l"(r) : "f"(x)); return r;
}
__device__ __forceinline__ u64 pack2(float lo, float hi) {
    u64 r; asm("mov.b64 %0, {%1, %2};" : "=l"(r) : "f"(lo), "f"(hi)); return r;
}
__device__ __forceinline__ void fma2(u64& a, u64 x, u64 y) {
    asm("fma.rn.f32x2 %0, %1, %2, %0;" : "+l"(a) : "l"(x), "l"(y));
}
__device__ __forceinline__ u64 add2(u64 x, u64 y) {
    u64 r; asm("add.rn.f32x2 %0, %1, %2;" : "=l"(r) : "l"(x), "l"(y)); return r;
}
__device__ __forceinline__ float2 unpack2(u64 v) {
    float2 r; asm("mov.b64 {%0, %1}, %2;" : "=f"(r.x), "=f"(r.y) : "l"(v)); return r;
}
__device__ __forceinline__ unsigned ld_acq(const unsigned* p) {
    unsigned v; asm volatile("ld.acquire.gpu.u32 %0, [%1];" : "=r"(v) : "l"(p) : "memory"); return v;
}
__device__ __forceinline__ unsigned atom_add_acqrel(unsigned* p, unsigned v) {
    unsigned o; asm volatile("atom.add.acq_rel.gpu.u32 %0, [%1], %2;" : "=r"(o) : "l"(p), "r"(v) : "memory"); return o;
}
__device__ __forceinline__ void st_rel(unsigned* p, unsigned v) {
    asm volatile("st.release.gpu.u32 [%0], %1;" :: "l"(p), "r"(v) : "memory");
}

#define WSLOT 25
#define NCHUNK 1088        // 64-token chunks: q 64, p 128, n 896
#define TOFS 64            // phase interleave offset (chunks)
#define NTICK (2*NCHUNK)
#define GRID_BLOCKS 592    // 148 SM * 4

__global__ __launch_bounds__(128, 4) void fused(
    const float* __restrict__ qh, const float* __restrict__ ph, const float* __restrict__ nh,
    const int* __restrict__ qw, const int* __restrict__ pw, const int* __restrict__ nwid,
    const float* __restrict__ projw, const float* __restrict__ projb,
    const float* __restrict__ simp, float* __restrict__ out)
{
    __shared__ u64 sw[192 * WSLOT];   // 38400 B weight table (pitch-25: conflict-free)
    __shared__ float impbuf[400];
    __shared__ float red[4];
    __shared__ float cf[64];
    __shared__ unsigned s_t;
    __shared__ int s_last;

    const int tid  = threadIdx.x;
    const int lane = tid & 31;
    const int wrp  = tid >> 5;
    const int sub  = lane & 7;
    const int grp  = lane >> 3;

    for (int idx = tid; idx < 768 * 6; idx += 128) {
        int d = idx / 6, j = idx % 6;
        sw[(d >> 2) * WSLOT + j * 4 + (d & 3)] = pack2(projw[d * 12 + 2 * j], projw[d * 12 + 2 * j + 1]);
    }
    __syncthreads();

    for (;;) {
        if (tid == 0) s_t = atomicAdd(&g_ctrl[0], 1u);
        __syncthreads();
        const unsigned t = s_t;
        __syncthreads();
        if (t >= NTICK) break;

        // ---- ticket -> (phase, chunk): first TOFS are phase1, then alternate
        int phase, c;
        if (t < TOFS) { phase = 0; c = (int)t; }
        else if (t < TOFS + 2 * (NCHUNK - TOFS)) {
            int d = (int)t - TOFS;
            phase = d & 1;
            c = phase ? (d >> 1) : (TOFS + (d >> 1));
        } else { phase = 1; c = NCHUNK - TOFS + ((int)t - (TOFS + 2 * (NCHUNK - TOFS))); }

        // ---- chunk -> tensor/sample/slab
        const float* hid; const int* wid; int L, m, slab, wbW, s, tgt; float* po;
        if (c < 64)       { hid = qh; wid = qw;   L = 256; m = c >> 2;  slab = c & 3;
                            wbW = m * 200;        s = m;      tgt = 4; po = out + OFF_QPOOL + m * 768; }
        else if (c < 192) { int cc = c - 64;  hid = ph; wid = pw;   L = 512; m = cc >> 3; slab = cc & 7;
                            wbW = 3200 + m * 400; s = 16 + m; tgt = 8; po = out + OFF_PPOOL + m * 768; }
        else              { int cc = c - 192; hid = nh; wid = nwid; L = 512; m = cc >> 3; slab = cc & 7;
                            wbW = 9600 + m * 400; s = 32 + m; tgt = 8; po = out + OFF_NPOOL + m * 768; }
        const int tokBase0 = m * L + slab * 64;

        if (phase == 0) {
            // ======== phase1: this warp does 16 tokens ========
            const int tokW = tokBase0 + wrp * 16;
            const float* hb = hid + (size_t)tokW * 768 + sub * 4;

            u64 acc[4][6];
            #pragma unroll
            for (int tt = 0; tt < 4; tt++)
                #pragma unroll
                for (int j = 0; j < 6; j++) acc[tt][j] = 0ull;

            #pragma unroll 2
            for (int i = 0; i < 24; i++) {
                float ha[4][4];
                #pragma unroll
                for (int tt = 0; tt < 4; tt++) {
                    float4 v = *(const float4*)(hb + (size_t)(grp + 4 * tt) * 768 + i * 32);
                    ha[tt][0] = v.x; ha[tt][1] = v.y; ha[tt][2] = v.z; ha[tt][3] = v.w;
                }
                const u64* wr = sw + (sub + 8 * i) * WSLOT;
                #pragma unroll
                for (int k = 0; k < 4; k++) {
                    u64 w0 = wr[0 * 4 + k], w1 = wr[1 * 4 + k], w2 = wr[2 * 4 + k];
                    u64 w3 = wr[3 * 4 + k], w4 = wr[4 * 4 + k], w5 = wr[5 * 4 + k];
                    #pragma unroll
                    for (int tt = 0; tt < 4; tt++) {
                        u64 h2 = pack2(ha[tt][k]);
                        fma2(acc[tt][0], h2, w0); fma2(acc[tt][1], h2, w1);
                        fma2(acc[tt][2], h2, w2); fma2(acc[tt][3], h2, w3);
                        fma2(acc[tt][4], h2, w4); fma2(acc[tt][5], h2, w5);
                    }
                }
            }
            #pragma unroll
            for (int tt = 0; tt < 4; tt++)
                #pragma unroll
                for (int j = 0; j < 6; j++) {
                    u64 v = acc[tt][j];
                    v = add2(v, __shfl_xor_sync(0xffffffffu, v, 1));
                    v = add2(v, __shfl_xor_sync(0xffffffffu, v, 2));
                    v = add2(v, __shfl_xor_sync(0xffffffffu, v, 4));
                    acc[tt][j] = v;
                }
            if (sub == 0) {
                #pragma unroll
                for (int tt = 0; tt < 4; tt++) {
                    int tok = tokW + grp + 4 * tt;
                    float* ls = g_acc + (size_t)(wbW + wid[tok]) * 13;
                    #pragma unroll
                    for (int j = 0; j < 6; j++) {
                        float2 f = unpack2(acc[tt][j]);
                        atomicAdd(ls + 2 * j,     f.x);
                        atomicAdd(ls + 2 * j + 1, f.y);
                    }
                    atomicAdd(ls + 12, 1.0f);
                }
            }
            __syncthreads();
            if (tid == 0) {
                unsigned old = atom_add_acqrel(&g_ctrl[16 + s], 1u);
                s_last = (old == (unsigned)(tgt - 1));
            }
            __syncthreads();

            if (s_last) {
                // ======== inline kB for sample s ========
                const int W = (s < 16) ? 200 : 400;
                float* lout = (s < 16) ? out + OFF_QLOG + s * 200 * 12
                            : (s < 32) ? out + OFF_PLOG + (s - 16) * 400 * 12 : nullptr;
                float b[12], si[12];
                #pragma unroll
                for (int k = 0; k < 12; k++) { b[k] = projb[k]; si[k] = simp[k]; }

                for (int w = tid; w < W; w += 128) {
                    const float* ls = g_acc + (size_t)(wbW + w) * 13;
                    float cnt = __ldcg(ls + 12);
                    float imp;
                    if (cnt > 0.f) {
                        float l[12], mx = -1e30f;
                        float invc = 1.f / cnt;
                        #pragma unroll
                        for (int k = 0; k < 12; k++) {
                            l[k] = __ldcg(ls + k) * invc + b[k];
                            mx = fmaxf(mx, l[k]);
                        }
                        float se = 0.f, ai = 0.f;
                        #pragma unroll
                        for (int k = 0; k < 12; k++) {
                            float e = __expf(l[k] - mx);
                            se += e; ai += e * si[k];
                        }
                        imp = ai / se;
                        if (lout) {
                            #pragma unroll
                            for (int k = 0; k < 12; k++) lout[w * 12 + k] = l[k];
                        }
                    } else {
                        imp = -1e4f;
                        if (lout) {
                            #pragma unroll
                            for (int k = 0; k < 12; k++) lout[w * 12 + k] = 0.f;
                        }
                    }
                    impbuf[w] = imp;
                }
                __syncthreads();

                float mx = -1e30f;
                for (int w = tid; w < W; w += 128) mx = fmaxf(mx, impbuf[w]);
                #pragma unroll
                for (int o = 16; o; o >>= 1) mx = fmaxf(mx, __shfl_xor_sync(0xffffffffu, mx, o));
                if (lane == 0) red[wrp] = mx;
                __syncthreads();
                mx = fmaxf(fmaxf(red[0], red[1]), fmaxf(red[2], red[3]));
                __syncthreads();

                float se = 0.f;
                for (int w = tid; w < W; w += 128) se += __expf(impbuf[w] - mx);
                #pragma unroll
                for (int o = 16; o; o >>= 1) se += __shfl_xor_sync(0xffffffffu, se, o);
                if (lane == 0) red[wrp] = se;
                __syncthreads();
                se = red[0] + red[1] + red[2] + red[3];
                const float inv = 1.f / se;

                for (int w = tid; w < W; w += 128) {
                    float cnt = __ldcg(g_acc + (size_t)(wbW + w) * 13 + 12);
                    g_coef[wbW + w] = (cnt > 0.f) ? (__expf(impbuf[w] - mx) * inv) / cnt : 0.f;
                }
                __syncthreads();
                if (tid == 0) st_rel(&g_ctrl[256 + s], 1u);
            }
        } else {
            // ======== phase3: 64-token pooling chunk ========
            if (tid == 0) {
                while (ld_acq(&g_ctrl[256 + s]) == 0u) __nanosleep(128);
            }
            __syncthreads();
            ld_acq(&g_ctrl[256 + s]);   // per-thread acquire

            if (tid < 64) cf[tid] = __ldcg(&g_coef[wbW + wid[tokBase0 + tid]]);
            __syncthreads();

            const float* hp = hid + (size_t)tokBase0 * 768;
            const float* p0 = hp + tid * 4;
            const float* p1 = hp + 512 + tid * 4;   // tid<64 only
            float a0 = 0, a1 = 0, a2 = 0, a3 = 0;
            float b0 = 0, b1 = 0, b2 = 0, b3 = 0;
            #pragma unroll 4
            for (int tk = 0; tk < 64; tk++) {
                float cc = cf[tk];
                float4 v = *(const float4*)(p0 + (size_t)tk * 768);
                a0 += cc * v.x; a1 += cc * v.y; a2 += cc * v.z; a3 += cc * v.w;
                if (tid < 64) {
                    float4 u = *(const float4*)(p1 + (size_t)tk * 768);
                    b0 += cc * u.x; b1 += cc * u.y; b2 += cc * u.z; b3 += cc * u.w;
                }
            }
            float* o = po + tid * 4;
            atomicAdd(o + 0, a0); atomicAdd(o + 1, a1);
            atomicAdd(o + 2, a2); atomicAdd(o + 3, a3);
            if (tid < 64) {
                float* o2 = po + 512 + tid * 4;
                atomicAdd(o2 + 0, b0); atomicAdd(o2 + 1, b1);
                atomicAdd(o2 + 2, b2); atomicAdd(o2 + 3, b3);
            }
            __syncthreads();   // cf reuse protection
        }
    }
}

// ---------------------------------------------------------------------------
extern "C" void kernel_launch(void* const* d_in, const int* in_sizes, int n_in,
                              void* d_out, int out_size)
{
    const float* qh    = (const float*)d_in[0];
    const float* ph    = (const float*)d_in[1];
    const float* nh    = (const float*)d_in[2];
    const float* projw = (const float*)d_in[3];
    const float* projb = (const float*)d_in[4];
    const float* simp  = (const float*)d_in[5];
    const int*   qw    = (const int*)d_in[6];
    const int*   pw    = (const int*)d_in[7];
    const int*   nwid  = (const int*)d_in[8];
    float* out = (float*)d_out;

    // best-effort: maximize smem carveout for occupancy (idempotent; errors ignored)
    cudaFuncSetAttribute(fused, cudaFuncAttributePreferredSharedMemoryCarveout, 100);

    void* pacc = nullptr; cudaGetSymbolAddress(&pacc, g_acc);
    void* pctl = nullptr; cudaGetSymbolAddress(&pctl, g_ctrl);
    cudaMemsetAsync(pacc, 0, sizeof(float) * TOTAL_WORDS * 13);
    cudaMemsetAsync(pctl, 0, sizeof(unsigned) * 512);
    cudaMemsetAsync(out + OFF_QPOOL, 0, sizeof(float) * 24576);   // q_pooled + p_pooled
    cudaMemsetAsync(out + OFF_NPOOL, 0, sizeof(float) * 86016);   // n_pooled

    fused<<<GRID_BLOCKS, 128>>>(qh, ph, nh, qw, pw, nwid, projw, projb, simp, out);
}

// round 5
// speedup vs baseline: 1.5816x; 1.5816x over previous
#include <cuda_runtime.h>

// ---------------------------------------------------------------------------
// B=16, N=7, Lq=256, Lp=512, D=768, S=12, Wq=200, Wp=400
// word slots: q 3200, p 6400, n 44800 -> 54400
// out floats: q_pooled[0,12288) p_pooled[12288,24576)
//             q_logits[24576,62976) p_logits[62976,139776) n_pooled[139776,225792)
// ---------------------------------------------------------------------------
#define TOTAL_WORDS 54400
#define OFF_QPOOL 0
#define OFF_PPOOL 12288
#define OFF_QLOG  24576
#define OFF_PLOG  62976
#define OFF_NPOOL 139776

// g_acc[w*13 + 0..11] = logit sums, [w*13+12] = count
__device__ float g_acc[TOTAL_WORDS * 13];
__device__ float g_coef[TOTAL_WORDS];

typedef unsigned long long u64;

__device__ __forceinline__ u64 pack2(float x) {
    u64 r; asm("mov.b64 %0, {%1, %1};" : "=l"(r) : "f"(x)); return r;
}
__device__ __forceinline__ u64 pack2(float lo, float hi) {
    u64 r; asm("mov.b64 %0, {%1, %2};" : "=l"(r) : "f"(lo), "f"(hi)); return r;
}
__device__ __forceinline__ void fma2(u64& a, u64 x, u64 y) {
    asm("fma.rn.f32x2 %0, %1, %2, %0;" : "+l"(a) : "l"(x), "l"(y));
}
__device__ __forceinline__ u64 add2(u64 x, u64 y) {
    u64 r; asm("add.rn.f32x2 %0, %1, %2;" : "=l"(r) : "l"(x), "l"(y)); return r;
}
__device__ __forceinline__ float2 unpack2(u64 v) {
    float2 r; asm("mov.b64 {%0, %1}, %2;" : "=f"(r.x), "=f"(r.y) : "l"(v)); return r;
}

// ---------------------------------------------------------------------------
// Kernel A: per-token projection h[768]@W[768x12] + segment atomics.
// Geometry: sub = lane&7 covers d = sub*4 + 32*i + k (i 0..23, k 0..3)
//           grp = lane>>3, tokens = grp + 4*tt, tt 0..3 -> 16 tokens/pass.
// Explicit software pipeline: iteration i computes while i+1's 4 LDG.128
// are in flight (double-buffered h registers) -> DRAM latency hidden.
// Weights: smem chunks pitch 26 u64 (39936B). sub byte offsets mod 128:
// {0,80,32,112,64,16,96,48} -> conflict-free LDS.128 (v2.u64).
// Passes: 69632/16 = 4352; grid 544*4 warps = 2176 -> exactly 2 passes/warp.
// ---------------------------------------------------------------------------
#define WSLOT 26
#define NPASS_TOTAL 4352
#define KA_BLOCKS 544

#define KA_COMPUTE(I)                                                          \
    {                                                                          \
        const u64* wr = swl + (I) * (8 * WSLOT);                               \
        _Pragma("unroll")                                                      \
        for (int j = 0; j < 6; j++) {                                          \
            ulonglong2 wA = *(const ulonglong2*)(wr + j * 4);                  \
            ulonglong2 wB = *(const ulonglong2*)(wr + j * 4 + 2);              \
            _Pragma("unroll")                                                  \
            for (int tt = 0; tt < 4; tt++) {                                   \
                fma2(acc[tt][j], h2[tt][0], wA.x);                             \
                fma2(acc[tt][j], h2[tt][1], wA.y);                             \
                fma2(acc[tt][j], h2[tt][2], wB.x);                             \
                fma2(acc[tt][j], h2[tt][3], wB.y);                             \
            }                                                                  \
        }                                                                      \
    }

#define KA_PACK(v0, v1, v2, v3)                                                \
    {                                                                          \
        h2[0][0] = pack2(v0.x); h2[0][1] = pack2(v0.y);                        \
        h2[0][2] = pack2(v0.z); h2[0][3] = pack2(v0.w);                        \
        h2[1][0] = pack2(v1.x); h2[1][1] = pack2(v1.y);                        \
        h2[1][2] = pack2(v1.z); h2[1][3] = pack2(v1.w);                        \
        h2[2][0] = pack2(v2.x); h2[2][1] = pack2(v2.y);                        \
        h2[2][2] = pack2(v2.z); h2[2][3] = pack2(v2.w);                        \
        h2[3][0] = pack2(v3.x); h2[3][1] = pack2(v3.y);                        \
        h2[3][2] = pack2(v3.z); h2[3][3] = pack2(v3.w);                        \
    }

__global__ __launch_bounds__(128, 4) void kA(
    const float* __restrict__ qh, const float* __restrict__ ph, const float* __restrict__ nh,
    const int* __restrict__ qw, const int* __restrict__ pw, const int* __restrict__ nwid,
    const float* __restrict__ projw)
{
    __shared__ u64 sw[192 * WSLOT];   // 39936 bytes
    for (int idx = threadIdx.x; idx < 768 * 6; idx += 128) {
        int d = idx / 6, j = idx % 6;
        sw[(d >> 2) * WSLOT + j * 4 + (d & 3)] =
            pack2(projw[d * 12 + 2 * j], projw[d * 12 + 2 * j + 1]);
    }
    __syncthreads();

    const int lane = threadIdx.x & 31;
    const int sub  = lane & 7;
    const int grp  = lane >> 3;
    const int gw   = (blockIdx.x * blockDim.x + threadIdx.x) >> 5;
    const int nwarps = (KA_BLOCKS * 128) >> 5;
    const u64* swl = sw + sub * WSLOT;

    for (int p = gw; p < NPASS_TOTAL; p += nwarps) {
        const float* hid; const int* wid; int logL, W, wb, lp;
        if (p < 256)      { hid = qh; wid = qw;   logL = 8; W = 200; wb = 0;    lp = p; }
        else if (p < 768) { hid = ph; wid = pw;   logL = 9; W = 400; wb = 3200; lp = p - 256; }
        else              { hid = nh; wid = nwid; logL = 9; W = 400; wb = 9600; lp = p - 768; }

        const int tokBase = lp << 4;                 // 16 tokens
        const int m = tokBase >> logL;
        const float* hbg = hid + (size_t)tokBase * 768 + (size_t)grp * 768 + sub * 4;

        u64 acc[4][6];
        #pragma unroll
        for (int tt = 0; tt < 4; tt++)
            #pragma unroll
            for (int j = 0; j < 6; j++) acc[tt][j] = 0ull;

        u64 h2[4][4];
        {
            float4 c0 = __ldcs((const float4*)(hbg));
            float4 c1 = __ldcs((const float4*)(hbg + 3072));
            float4 c2 = __ldcs((const float4*)(hbg + 6144));
            float4 c3 = __ldcs((const float4*)(hbg + 9216));
            KA_PACK(c0, c1, c2, c3);
        }

        #pragma unroll 2
        for (int i = 0; i < 23; i++) {
            // prefetch i+1 while computing i
            float4 n0 = __ldcs((const float4*)(hbg +        (i + 1) * 32));
            float4 n1 = __ldcs((const float4*)(hbg + 3072 + (i + 1) * 32));
            float4 n2 = __ldcs((const float4*)(hbg + 6144 + (i + 1) * 32));
            float4 n3 = __ldcs((const float4*)(hbg + 9216 + (i + 1) * 32));
            KA_COMPUTE(i);
            KA_PACK(n0, n1, n2, n3);
        }
        KA_COMPUTE(23);

        // reduce across the 8 sub-lanes (xor 1,2,4 stay inside the octet)
        #pragma unroll
        for (int tt = 0; tt < 4; tt++)
            #pragma unroll
            for (int j = 0; j < 6; j++) {
                u64 v = acc[tt][j];
                v = add2(v, __shfl_xor_sync(0xffffffffu, v, 1));
                v = add2(v, __shfl_xor_sync(0xffffffffu, v, 2));
                v = add2(v, __shfl_xor_sync(0xffffffffu, v, 4));
                acc[tt][j] = v;
            }

        if (sub == 0) {
            #pragma unroll
            for (int tt = 0; tt < 4; tt++) {
                int tok = tokBase + grp + 4 * tt;
                float* ls = g_acc + (size_t)(wb + m * W + wid[tok]) * 13;
                #pragma unroll
                for (int j = 0; j < 6; j++) {
                    float2 f = unpack2(acc[tt][j]);
                    atomicAdd(ls + 2 * j,     f.x);
                    atomicAdd(ls + 2 * j + 1, f.y);
                }
                atomicAdd(ls + 12, 1.0f);
            }
        }
    }
}

// ---------------------------------------------------------------------------
// Kernel B: per sample — scope softmax -> importance, masked word softmax ->
// per-word coefficient weight/count; writes q/p logits. 144 blocks x 128.
// ---------------------------------------------------------------------------
__global__ __launch_bounds__(128) void kB(const float* __restrict__ projb,
                                          const float* __restrict__ simp,
                                          float* __restrict__ out)
{
    const int blk = blockIdx.x;
    int W, wb; float* lout = nullptr;
    if (blk < 16)      { W = 200; wb = blk * 200;                    lout = out + OFF_QLOG + blk * 200 * 12; }
    else if (blk < 32) { int m = blk - 16; W = 400; wb = 3200 + m * 400; lout = out + OFF_PLOG + m * 400 * 12; }
    else               { int m = blk - 32; W = 400; wb = 9600 + m * 400; }

    __shared__ float impbuf[400];
    __shared__ float red[4];
    const int tid = threadIdx.x;

    float b[12], si[12];
    #pragma unroll
    for (int s = 0; s < 12; s++) { b[s] = projb[s]; si[s] = simp[s]; }

    for (int w = tid; w < W; w += 128) {
        const float* ls = g_acc + (size_t)(wb + w) * 13;
        float c = ls[12];
        float imp;
        if (c > 0.f) {
            float l[12], mx = -1e30f;
            float invc = 1.f / c;
            #pragma unroll
            for (int s = 0; s < 12; s++) {
                l[s] = ls[s] * invc + b[s];
                mx = fmaxf(mx, l[s]);
            }
            float se = 0.f, ai = 0.f;
            #pragma unroll
            for (int s = 0; s < 12; s++) {
                float e = __expf(l[s] - mx);
                se += e; ai += e * si[s];
            }
            imp = ai / se;
            if (lout) {
                #pragma unroll
                for (int s = 0; s < 12; s++) lout[w * 12 + s] = l[s];
            }
        } else {
            imp = -1e4f;
            if (lout) {
                #pragma unroll
                for (int s = 0; s < 12; s++) lout[w * 12 + s] = 0.f;
            }
        }
        impbuf[w] = imp;
    }
    __syncthreads();

    float mx = -1e30f;
    for (int w = tid; w < W; w += 128) mx = fmaxf(mx, impbuf[w]);
    #pragma unroll
    for (int o = 16; o; o >>= 1) mx = fmaxf(mx, __shfl_xor_sync(0xffffffffu, mx, o));
    if ((tid & 31) == 0) red[tid >> 5] = mx;
    __syncthreads();
    mx = fmaxf(fmaxf(red[0], red[1]), fmaxf(red[2], red[3]));
    __syncthreads();

    float se = 0.f;
    for (int w = tid; w < W; w += 128) se += __expf(impbuf[w] - mx);
    #pragma unroll
    for (int o = 16; o; o >>= 1) se += __shfl_xor_sync(0xffffffffu, se, o);
    if ((tid & 31) == 0) red[tid >> 5] = se;
    __syncthreads();
    se = red[0] + red[1] + red[2] + red[3];
    const float inv = 1.f / se;

    for (int w = tid; w < W; w += 128) {
        float c = g_acc[(size_t)(wb + w) * 13 + 12];
        g_coef[wb + w] = (c > 0.f) ? (__expf(impbuf[w] - mx) * inv) / c : 0.f;
    }
}

// ---------------------------------------------------------------------------
// Kernel C: pooled[m,:] += sum over 64-token slab coef[m, wid] * h[m,tok,:]
// 1088 blocks x 192 threads, float4/thread, streaming loads, unroll 8.
// ---------------------------------------------------------------------------
__global__ __launch_bounds__(192) void kC(
    const float* __restrict__ qh, const float* __restrict__ ph, const float* __restrict__ nh,
    const int* __restrict__ qw, const int* __restrict__ pw, const int* __restrict__ nwid,
    float* __restrict__ out)
{
    const int blk = blockIdx.x;
    const float* hid; const int* wid; int L, wb, m, slab; float* po;
    if (blk < 64)       { m = blk >> 2;  slab = blk & 3; hid = qh; wid = qw;   L = 256; wb = m * 200;        po = out + OFF_QPOOL + m * 768; }
    else if (blk < 192) { int b2 = blk - 64;  m = b2 >> 3; slab = b2 & 7; hid = ph; wid = pw;   L = 512; wb = 3200 + m * 400; po = out + OFF_PPOOL + m * 768; }
    else                { int b2 = blk - 192; m = b2 >> 3; slab = b2 & 7; hid = nh; wid = nwid; L = 512; wb = 9600 + m * 400; po = out + OFF_NPOOL + m * 768; }

    __shared__ float cf[64];
    const int tid = threadIdx.x;
    const int t0 = slab * 64;
    if (tid < 64) cf[tid] = g_coef[wb + wid[m * L + t0 + tid]];
    __syncthreads();

    const float* hp = hid + (size_t)(m * L + t0) * 768 + tid * 4;
    float ax = 0.f, ay = 0.f, az = 0.f, aw = 0.f;
    #pragma unroll 8
    for (int t = 0; t < 64; t++) {
        float c = cf[t];
        float4 v = __ldcs((const float4*)(hp + (size_t)t * 768));
        ax += c * v.x; ay += c * v.y; az += c * v.z; aw += c * v.w;
    }
    float* o = po + tid * 4;
    atomicAdd(o + 0, ax);
    atomicAdd(o + 1, ay);
    atomicAdd(o + 2, az);
    atomicAdd(o + 3, aw);
}

// ---------------------------------------------------------------------------
extern "C" void kernel_launch(void* const* d_in, const int* in_sizes, int n_in,
                              void* d_out, int out_size)
{
    const float* qh    = (const float*)d_in[0];
    const float* ph    = (const float*)d_in[1];
    const float* nh    = (const float*)d_in[2];
    const float* projw = (const float*)d_in[3];
    const float* projb = (const float*)d_in[4];
    const float* simp  = (const float*)d_in[5];
    const int*   qw    = (const int*)d_in[6];
    const int*   pw    = (const int*)d_in[7];
    const int*   nwid  = (const int*)d_in[8];
    float* out = (float*)d_out;

    void* pacc = nullptr; cudaGetSymbolAddress(&pacc, g_acc);
    cudaMemsetAsync(pacc, 0, sizeof(float) * TOTAL_WORDS * 13);
    cudaMemsetAsync(out + OFF_QPOOL, 0, sizeof(float) * 24576);   // q_pooled + p_pooled
    cudaMemsetAsync(out + OFF_NPOOL, 0, sizeof(float) * 86016);   // n_pooled

    kA<<<KA_BLOCKS, 128>>>(qh, ph, nh, qw, pw, nwid, projw);
    kB<<<144, 128>>>(projb, simp, out);
    kC<<<1088, 192>>>(qh, ph, nh, qw, pw, nwid, out);
}

// round 6
// speedup vs baseline: 1.6632x; 1.0516x over previous
#include <cuda_runtime.h>

// ---------------------------------------------------------------------------
// B=16, N=7, Lq=256, Lp=512, D=768, S=12, Wq=200, Wp=400
// word slots: q 3200, p 6400, n 44800 -> 54400
// out floats: q_pooled[0,12288) p_pooled[12288,24576)
//             q_logits[24576,62976) p_logits[62976,139776) n_pooled[139776,225792)
// ---------------------------------------------------------------------------
#define TOTAL_WORDS 54400
#define OFF_QPOOL 0
#define OFF_PPOOL 12288
#define OFF_QLOG  24576
#define OFF_PLOG  62976
#define OFF_NPOOL 139776

// g_acc[w*13 + 0..11] = logit sums, [w*13+12] = count
__device__ float g_acc[TOTAL_WORDS * 13];
__device__ float g_coef[TOTAL_WORDS];

typedef unsigned long long u64;

__device__ __forceinline__ u64 pack2(float x) {
    u64 r; asm("mov.b64 %0, {%1, %1};" : "=l"(r) : "f"(x)); return r;
}
__device__ __forceinline__ u64 pack2(float lo, float hi) {
    u64 r; asm("mov.b64 %0, {%1, %2};" : "=l"(r) : "f"(lo), "f"(hi)); return r;
}
__device__ __forceinline__ void fma2(u64& a, u64 x, u64 y) {
    asm("fma.rn.f32x2 %0, %1, %2, %0;" : "+l"(a) : "l"(x), "l"(y));
}
__device__ __forceinline__ u64 add2(u64 x, u64 y) {
    u64 r; asm("add.rn.f32x2 %0, %1, %2;" : "=l"(r) : "l"(x), "l"(y)); return r;
}
__device__ __forceinline__ float2 unpack2(u64 v) {
    float2 r; asm("mov.b64 {%0, %1}, %2;" : "=f"(r.x), "=f"(r.y) : "l"(v)); return r;
}

// ---------------------------------------------------------------------------
// Kernel A: per-token projection h[768]@W[768x12] + segment atomics.
// Geometry: sub = lane&7 covers d = sub*4 + 32*i + k (i 0..23, k 0..3)
//           grp = lane>>3, tokens = grp + 4*tt, tt 0..3 -> 16 tokens/pass.
// Software pipeline: 3 rotating register buffers (A,B,C), loads issued
// 2-3 compute blocks before their consumer -> DRAM latency fully shadowed.
// No buffer-copy movs: rotation by role in an unroll-3 body.
// Weights: smem chunks [c][k*6+j], pitch 26 u64. Per k-step: 3x LDS.128,
// sub byte offsets mod 128 = {0,80,32,112,64,16,96,48} -> conflict-free.
// Passes: 69632/16 = 4352; grid 544*4 warps = 2176 -> exactly 2 passes/warp.
// ---------------------------------------------------------------------------
#define WSLOT 26
#define NPASS_TOTAL 4352
#define KA_BLOCKS 544

#define KA_LD(I, V0, V1, V2, V3)                                               \
    {                                                                          \
        V0 = __ldcs((const float4*)(hbg +        (I) * 32));                   \
        V1 = __ldcs((const float4*)(hbg + 3072 + (I) * 32));                   \
        V2 = __ldcs((const float4*)(hbg + 6144 + (I) * 32));                   \
        V3 = __ldcs((const float4*)(hbg + 9216 + (I) * 32));                   \
    }

#define KA_COMPUTE(I, A0, A1, A2, A3)                                          \
    {                                                                          \
        const u64* wr = swl + (I) * (8 * WSLOT);                               \
        _Pragma("unroll")                                                      \
        for (int k = 0; k < 4; k++) {                                          \
            u64 h0 = pack2(((const float*)&A0)[k]);                            \
            u64 h1 = pack2(((const float*)&A1)[k]);                            \
            u64 hv2 = pack2(((const float*)&A2)[k]);                           \
            u64 h3 = pack2(((const float*)&A3)[k]);                            \
            ulonglong2 w01 = *(const ulonglong2*)(wr + k * 6);                 \
            ulonglong2 w23 = *(const ulonglong2*)(wr + k * 6 + 2);             \
            ulonglong2 w45 = *(const ulonglong2*)(wr + k * 6 + 4);             \
            fma2(acc[0][0], h0, w01.x); fma2(acc[0][1], h0, w01.y);            \
            fma2(acc[0][2], h0, w23.x); fma2(acc[0][3], h0, w23.y);            \
            fma2(acc[0][4], h0, w45.x); fma2(acc[0][5], h0, w45.y);            \
            fma2(acc[1][0], h1, w01.x); fma2(acc[1][1], h1, w01.y);            \
            fma2(acc[1][2], h1, w23.x); fma2(acc[1][3], h1, w23.y);            \
            fma2(acc[1][4], h1, w45.x); fma2(acc[1][5], h1, w45.y);            \
            fma2(acc[2][0], hv2, w01.x); fma2(acc[2][1], hv2, w01.y);          \
            fma2(acc[2][2], hv2, w23.x); fma2(acc[2][3], hv2, w23.y);          \
            fma2(acc[2][4], hv2, w45.x); fma2(acc[2][5], hv2, w45.y);          \
            fma2(acc[3][0], h3, w01.x); fma2(acc[3][1], h3, w01.y);            \
            fma2(acc[3][2], h3, w23.x); fma2(acc[3][3], h3, w23.y);            \
            fma2(acc[3][4], h3, w45.x); fma2(acc[3][5], h3, w45.y);            \
        }                                                                      \
    }

__global__ __launch_bounds__(128, 4) void kA(
    const float* __restrict__ qh, const float* __restrict__ ph, const float* __restrict__ nh,
    const int* __restrict__ qw, const int* __restrict__ pw, const int* __restrict__ nwid,
    const float* __restrict__ projw)
{
    __shared__ __align__(16) u64 sw[192 * WSLOT];   // 39936 bytes
    for (int idx = threadIdx.x; idx < 768 * 6; idx += 128) {
        int d = idx / 6, j = idx % 6;
        sw[(d >> 2) * WSLOT + (d & 3) * 6 + j] =
            pack2(projw[d * 12 + 2 * j], projw[d * 12 + 2 * j + 1]);
    }
    __syncthreads();

    const int lane = threadIdx.x & 31;
    const int sub  = lane & 7;
    const int grp  = lane >> 3;
    const int gw   = (blockIdx.x * blockDim.x + threadIdx.x) >> 5;
    const int nwarps = (KA_BLOCKS * 128) >> 5;
    const u64* swl = sw + sub * WSLOT;

    for (int p = gw; p < NPASS_TOTAL; p += nwarps) {
        const float* hid; const int* wid; int logL, W, wb, lp;
        if (p < 256)      { hid = qh; wid = qw;   logL = 8; W = 200; wb = 0;    lp = p; }
        else if (p < 768) { hid = ph; wid = pw;   logL = 9; W = 400; wb = 3200; lp = p - 256; }
        else              { hid = nh; wid = nwid; logL = 9; W = 400; wb = 9600; lp = p - 768; }

        const int tokBase = lp << 4;                 // 16 tokens
        const int m = tokBase >> logL;
        const float* hbg = hid + (size_t)tokBase * 768 + (size_t)grp * 768 + sub * 4;

        u64 acc[4][6];
        #pragma unroll
        for (int tt = 0; tt < 4; tt++)
            #pragma unroll
            for (int j = 0; j < 6; j++) acc[tt][j] = 0ull;

        float4 A0, A1, A2, A3, B0, B1, B2, B3, C0, C1, C2, C3;
        KA_LD(0, A0, A1, A2, A3);
        KA_LD(1, B0, B1, B2, B3);

        // 7 bodies: computes 0..20, loads 2..22  (each load issued 2-3
        // compute blocks before its consumer)
        #pragma unroll 1
        for (int i = 0; i < 21; i += 3) {
            KA_LD(i + 2, C0, C1, C2, C3);
            KA_COMPUTE(i, A0, A1, A2, A3);
            KA_LD(i + 3, A0, A1, A2, A3);
            KA_COMPUTE(i + 1, B0, B1, B2, B3);
            KA_LD(i + 4, B0, B1, B2, B3);
            KA_COMPUTE(i + 2, C0, C1, C2, C3);
        }
        KA_LD(23, C0, C1, C2, C3);
        KA_COMPUTE(21, A0, A1, A2, A3);
        KA_COMPUTE(22, B0, B1, B2, B3);
        KA_COMPUTE(23, C0, C1, C2, C3);

        // reduce across the 8 sub-lanes (xor 1,2,4 stay inside the octet)
        #pragma unroll
        for (int tt = 0; tt < 4; tt++)
            #pragma unroll
            for (int j = 0; j < 6; j++) {
                u64 v = acc[tt][j];
                v = add2(v, __shfl_xor_sync(0xffffffffu, v, 1));
                v = add2(v, __shfl_xor_sync(0xffffffffu, v, 2));
                v = add2(v, __shfl_xor_sync(0xffffffffu, v, 4));
                acc[tt][j] = v;
            }

        if (sub == 0) {
            #pragma unroll
            for (int tt = 0; tt < 4; tt++) {
                int tok = tokBase + grp + 4 * tt;
                float* ls = g_acc + (size_t)(wb + m * W + wid[tok]) * 13;
                #pragma unroll
                for (int j = 0; j < 6; j++) {
                    float2 f = unpack2(acc[tt][j]);
                    atomicAdd(ls + 2 * j,     f.x);
                    atomicAdd(ls + 2 * j + 1, f.y);
                }
                atomicAdd(ls + 12, 1.0f);
            }
        }
    }
}

// ---------------------------------------------------------------------------
// Kernel B: per sample — scope softmax -> importance, masked word softmax ->
// per-word coefficient weight/count; writes q/p logits. 144 blocks x 128.
// ---------------------------------------------------------------------------
__global__ __launch_bounds__(128) void kB(const float* __restrict__ projb,
                                          const float* __restrict__ simp,
                                          float* __restrict__ out)
{
    const int blk = blockIdx.x;
    int W, wb; float* lout = nullptr;
    if (blk < 16)      { W = 200; wb = blk * 200;                    lout = out + OFF_QLOG + blk * 200 * 12; }
    else if (blk < 32) { int m = blk - 16; W = 400; wb = 3200 + m * 400; lout = out + OFF_PLOG + m * 400 * 12; }
    else               { int m = blk - 32; W = 400; wb = 9600 + m * 400; }

    __shared__ float impbuf[400];
    __shared__ float red[4];
    const int tid = threadIdx.x;

    float b[12], si[12];
    #pragma unroll
    for (int s = 0; s < 12; s++) { b[s] = projb[s]; si[s] = simp[s]; }

    for (int w = tid; w < W; w += 128) {
        const float* ls = g_acc + (size_t)(wb + w) * 13;
        float c = ls[12];
        float imp;
        if (c > 0.f) {
            float l[12], mx = -1e30f;
            float invc = 1.f / c;
            #pragma unroll
            for (int s = 0; s < 12; s++) {
                l[s] = ls[s] * invc + b[s];
                mx = fmaxf(mx, l[s]);
            }
            float se = 0.f, ai = 0.f;
            #pragma unroll
            for (int s = 0; s < 12; s++) {
                float e = __expf(l[s] - mx);
                se += e; ai += e * si[s];
            }
            imp = ai / se;
            if (lout) {
                #pragma unroll
                for (int s = 0; s < 12; s++) lout[w * 12 + s] = l[s];
            }
        } else {
            imp = -1e4f;
            if (lout) {
                #pragma unroll
                for (int s = 0; s < 12; s++) lout[w * 12 + s] = 0.f;
            }
        }
        impbuf[w] = imp;
    }
    __syncthreads();

    float mx = -1e30f;
    for (int w = tid; w < W; w += 128) mx = fmaxf(mx, impbuf[w]);
    #pragma unroll
    for (int o = 16; o; o >>= 1) mx = fmaxf(mx, __shfl_xor_sync(0xffffffffu, mx, o));
    if ((tid & 31) == 0) red[tid >> 5] = mx;
    __syncthreads();
    mx = fmaxf(fmaxf(red[0], red[1]), fmaxf(red[2], red[3]));
    __syncthreads();

    float se = 0.f;
    for (int w = tid; w < W; w += 128) se += __expf(impbuf[w] - mx);
    #pragma unroll
    for (int o = 16; o; o >>= 1) se += __shfl_xor_sync(0xffffffffu, se, o);
    if ((tid & 31) == 0) red[tid >> 5] = se;
    __syncthreads();
    se = red[0] + red[1] + red[2] + red[3];
    const float inv = 1.f / se;

    for (int w = tid; w < W; w += 128) {
        float c = g_acc[(size_t)(wb + w) * 13 + 12];
        g_coef[wb + w] = (c > 0.f) ? (__expf(impbuf[w] - mx) * inv) / c : 0.f;
    }
}

// ---------------------------------------------------------------------------
// Kernel C: pooled[m,:] += sum over 64-token slab coef[m, wid] * h[m,tok,:]
// 1088 blocks x 192 threads, float4/thread, streaming loads, unroll 8.
// ---------------------------------------------------------------------------
__global__ __launch_bounds__(192) void kC(
    const float* __restrict__ qh, const float* __restrict__ ph, const float* __restrict__ nh,
    const int* __restrict__ qw, const int* __restrict__ pw, const int* __restrict__ nwid,
    float* __restrict__ out)
{
    const int blk = blockIdx.x;
    const float* hid; const int* wid; int L, wb, m, slab; float* po;
    if (blk < 64)       { m = blk >> 2;  slab = blk & 3; hid = qh; wid = qw;   L = 256; wb = m * 200;        po = out + OFF_QPOOL + m * 768; }
    else if (blk < 192) { int b2 = blk - 64;  m = b2 >> 3; slab = b2 & 7; hid = ph; wid = pw;   L = 512; wb = 3200 + m * 400; po = out + OFF_PPOOL + m * 768; }
    else                { int b2 = blk - 192; m = b2 >> 3; slab = b2 & 7; hid = nh; wid = nwid; L = 512; wb = 9600 + m * 400; po = out + OFF_NPOOL + m * 768; }

    __shared__ float cf[64];
    const int tid = threadIdx.x;
    const int t0 = slab * 64;
    if (tid < 64) cf[tid] = g_coef[wb + wid[m * L + t0 + tid]];
    __syncthreads();

    const float* hp = hid + (size_t)(m * L + t0) * 768 + tid * 4;
    float ax = 0.f, ay = 0.f, az = 0.f, aw = 0.f;
    #pragma unroll 8
    for (int t = 0; t < 64; t++) {
        float c = cf[t];
        float4 v = __ldcs((const float4*)(hp + (size_t)t * 768));
        ax += c * v.x; ay += c * v.y; az += c * v.z; aw += c * v.w;
    }
    float* o = po + tid * 4;
    atomicAdd(o + 0, ax);
    atomicAdd(o + 1, ay);
    atomicAdd(o + 2, az);
    atomicAdd(o + 3, aw);
}

// ---------------------------------------------------------------------------
extern "C" void kernel_launch(void* const* d_in, const int* in_sizes, int n_in,
                              void* d_out, int out_size)
{
    const float* qh    = (const float*)d_in[0];
    const float* ph    = (const float*)d_in[1];
    const float* nh    = (const float*)d_in[2];
    const float* projw = (const float*)d_in[3];
    const float* projb = (const float*)d_in[4];
    const float* simp  = (const float*)d_in[5];
    const int*   qw    = (const int*)d_in[6];
    const int*   pw    = (const int*)d_in[7];
    const int*   nwid  = (const int*)d_in[8];
    float* out = (float*)d_out;

    void* pacc = nullptr; cudaGetSymbolAddress(&pacc, g_acc);
    cudaMemsetAsync(pacc, 0, sizeof(float) * TOTAL_WORDS * 13);
    cudaMemsetAsync(out + OFF_QPOOL, 0, sizeof(float) * 24576);   // q_pooled + p_pooled
    cudaMemsetAsync(out + OFF_NPOOL, 0, sizeof(float) * 86016);   // n_pooled

    kA<<<KA_BLOCKS, 128>>>(qh, ph, nh, qw, pw, nwid, projw);
    kB<<<144, 128>>>(projb, simp, out);
    kC<<<1088, 192>>>(qh, ph, nh, qw, pw, nwid, out);
}